// round 4
// baseline (speedup 1.0000x reference)
#include <cuda_runtime.h>
#include <math.h>

#define SEQ   2048
#define HID   2048
#define HDIM  128
#define NHEAD 16
#define KVDIM 512
#define FFD   4096
#define NEXP  8
#define NASSIGN (2*SEQ)

#define BM  128
#define BN  128
#define BKK 16

// ---------------- scratch (device globals: allocation-free rule) ----------------
__device__ float g_x[SEQ*HID];        // rmsnorm1 out
__device__ float g_q[SEQ*HID];
__device__ float g_k[SEQ*KVDIM];
__device__ float g_v[SEQ*KVDIM];
__device__ float g_attn[SEQ*HID];     // attention output (pre O-proj)
__device__ float g_h[SEQ*HID];        // residual after attention
__device__ float g_x2[SEQ*HID];       // rmsnorm2 out
__device__ int   g_topi[SEQ*2];
__device__ float g_topv[SEQ*2];
__device__ int   g_tok[NASSIGN];
__device__ float g_wgt[NASSIGN];
__device__ int   g_cnt[NEXP];
__device__ int   g_off[NEXP];
__device__ float g_t1[NASSIGN*FFD];   // 64 MB: gate-proj then swiglu result
__device__ float g_t3[NASSIGN*FFD];   // 64 MB: up-proj

// ---------------- rmsnorm ----------------
__global__ void rmsnorm_kernel(const float* __restrict__ hidden,
                               const float* __restrict__ w, int mode)
{
    const float* in  = mode ? g_h  : hidden;
    float*       out = mode ? g_x2 : g_x;
    int row = blockIdx.x;
    const float* x = in + (size_t)row*HID;
    __shared__ float red[256];
    float ss = 0.f;
    for (int i = threadIdx.x; i < HID; i += 256) { float v = x[i]; ss += v*v; }
    red[threadIdx.x] = ss; __syncthreads();
    for (int s = 128; s > 0; s >>= 1) {
        if (threadIdx.x < s) red[threadIdx.x] += red[threadIdx.x+s];
        __syncthreads();
    }
    float rs = rsqrtf(red[0]/(float)HID + 1e-5f);
    float* o = out + (size_t)row*HID;
    for (int i = threadIdx.x; i < HID; i += 256) o[i] = x[i]*rs*w[i];
}

// ---------------- dense SGEMM: C = A * B^T (+ addend) ----------------
// mode 0: C=g_q A=g_x   N=2048 | 1: C=g_k N=512 | 2: C=g_v N=512 | 3: C=g_h A=g_attn (+hidden)
__global__ __launch_bounds__(256) void sgemm_dense(
    const float* __restrict__ Bmat, const float* __restrict__ addend,
    int mode, int N)
{
    const float* A = (mode==3) ? g_attn : g_x;
    float* C = (mode==0) ? g_q : (mode==1) ? g_k : (mode==2) ? g_v : g_h;
    const int K = HID;
    __shared__ float As[BKK][BM];
    __shared__ float Bs[BKK][BN];
    int tid = threadIdx.x;
    int m0 = blockIdx.y*BM, n0 = blockIdx.x*BN;
    int tx = tid & 15, ty = tid >> 4;
    int r0 = tid >> 2, kc = (tid & 3)*4;
    int r1 = r0 + 64;
    const float* Ap0 = A    + (size_t)(m0+r0)*K + kc;
    const float* Ap1 = A    + (size_t)(m0+r1)*K + kc;
    const float* Bp0 = Bmat + (size_t)(n0+r0)*K + kc;
    const float* Bp1 = Bmat + (size_t)(n0+r1)*K + kc;
    float acc[8][8];
    #pragma unroll
    for (int i=0;i<8;i++)
        #pragma unroll
        for (int j=0;j<8;j++) acc[i][j]=0.f;
    for (int k0=0;k0<K;k0+=BKK){
        float4 a0 = *(const float4*)(Ap0 + k0);
        float4 a1 = *(const float4*)(Ap1 + k0);
        float4 b0 = *(const float4*)(Bp0 + k0);
        float4 b1 = *(const float4*)(Bp1 + k0);
        As[kc+0][r0]=a0.x; As[kc+1][r0]=a0.y; As[kc+2][r0]=a0.z; As[kc+3][r0]=a0.w;
        As[kc+0][r1]=a1.x; As[kc+1][r1]=a1.y; As[kc+2][r1]=a1.z; As[kc+3][r1]=a1.w;
        Bs[kc+0][r0]=b0.x; Bs[kc+1][r0]=b0.y; Bs[kc+2][r0]=b0.z; Bs[kc+3][r0]=b0.w;
        Bs[kc+0][r1]=b1.x; Bs[kc+1][r1]=b1.y; Bs[kc+2][r1]=b1.z; Bs[kc+3][r1]=b1.w;
        __syncthreads();
        #pragma unroll
        for (int k=0;k<BKK;k++){
            float a[8], b[8];
            *(float4*)&a[0] = *(const float4*)&As[k][ty*8];
            *(float4*)&a[4] = *(const float4*)&As[k][ty*8+4];
            *(float4*)&b[0] = *(const float4*)&Bs[k][tx*8];
            *(float4*)&b[4] = *(const float4*)&Bs[k][tx*8+4];
            #pragma unroll
            for (int i=0;i<8;i++)
                #pragma unroll
                for (int j=0;j<8;j++)
                    acc[i][j] += a[i]*b[j];
        }
        __syncthreads();
    }
    #pragma unroll
    for (int i=0;i<8;i++){
        int row = m0 + ty*8 + i;
        float* cp = C + (size_t)row*N + n0 + tx*8;
        if (addend){
            const float* ap = addend + (size_t)row*N + n0 + tx*8;
            #pragma unroll
            for (int j=0;j<8;j++) cp[j] = acc[i][j] + ap[j];
        } else {
            #pragma unroll
            for (int j=0;j<8;j++) cp[j] = acc[i][j];
        }
    }
}

// ---------------- RoPE (in-place on g_q / g_k) ----------------
__global__ void rope_kernel(int isK)
{
    int ncols = isK ? KVDIM : HID;
    int half  = ncols >> 1;                 // pairs per row
    int idx = blockIdx.x*256 + threadIdx.x;
    if (idx >= SEQ*half) return;
    int t = idx / half;
    int p = idx - t*half;
    int head = p >> 6;                      // 64 pairs per head
    int d = p & 63;
    float* buf = isK ? g_k : g_q;
    int c1 = head*HDIM + d;
    float inv = expf(-(float)d * (9.210340371976184f/64.f)); // 10000^(-d/64)
    float ang = (float)t * inv;
    float cs = cosf(ang), sn = sinf(ang);
    float* b1 = buf + (size_t)t*ncols + c1;
    float x1 = b1[0], x2 = b1[64];
    b1[0]  = x1*cs - x2*sn;
    b1[64] = x2*cs + x1*sn;
}

// ---------------- flash attention (causal, GQA 4:1) ----------------
// grid (S/64, NHEAD), 256 threads; thread = (row 0..63, quarter 0..3 of D)
__global__ __launch_bounds__(256,1) void flash_attn_kernel()
{
    __shared__ float KV[64][128];
    int qt = blockIdx.x, h = blockIdx.y;
    int kvh = h >> 2;
    int tid = threadIdx.x;
    int row = tid >> 2;
    int quar = tid & 3;
    int qrow = qt*64 + row;
    const float scale = 0.08838834764831845f;   // 1/sqrt(128)
    float qreg[32];
    const float4* qp = (const float4*)&g_q[(size_t)qrow*HID + h*HDIM + quar*32];
    #pragma unroll
    for (int i=0;i<8;i++){
        float4 v = qp[i];
        qreg[4*i+0]=v.x*scale; qreg[4*i+1]=v.y*scale;
        qreg[4*i+2]=v.z*scale; qreg[4*i+3]=v.w*scale;
    }
    float m = -1e30f, l = 0.f;
    float o[32];
    #pragma unroll
    for (int i=0;i<32;i++) o[i]=0.f;

    for (int kt = 0; kt <= qt; kt++){
        int k0 = kt*64;
        __syncthreads();
        {   // stage K tile
            const float4* src = (const float4*)&g_k[(size_t)(k0+row)*KVDIM + kvh*HDIM + quar*32];
            float4* dst = (float4*)&KV[row][quar*32];
            #pragma unroll
            for (int i=0;i<8;i++) dst[i]=src[i];
        }
        __syncthreads();
        float s[64];
        #pragma unroll
        for (int j=0;j<64;j++){
            const float4* kp = (const float4*)&KV[j][quar*32];
            float acc = 0.f;
            #pragma unroll
            for (int i=0;i<8;i++){
                float4 kv = kp[i];
                acc += qreg[4*i+0]*kv.x + qreg[4*i+1]*kv.y
                     + qreg[4*i+2]*kv.z + qreg[4*i+3]*kv.w;
            }
            acc += __shfl_xor_sync(0xffffffffu, acc, 1);
            acc += __shfl_xor_sync(0xffffffffu, acc, 2);
            s[j] = acc;
        }
        if (kt == qt){
            #pragma unroll
            for (int j=0;j<64;j++) if (k0+j > qrow) s[j] = -1e30f;
        }
        float nm = m;
        #pragma unroll
        for (int j=0;j<64;j++) nm = fmaxf(nm, s[j]);
        float corr = __expf(m - nm);
        float ls = 0.f;
        #pragma unroll
        for (int j=0;j<64;j++){ s[j] = __expf(s[j]-nm); ls += s[j]; }
        l = l*corr + ls;
        #pragma unroll
        for (int i=0;i<32;i++) o[i] *= corr;
        m = nm;
        __syncthreads();
        {   // stage V tile into the same buffer
            const float4* src = (const float4*)&g_v[(size_t)(k0+row)*KVDIM + kvh*HDIM + quar*32];
            float4* dst = (float4*)&KV[row][quar*32];
            #pragma unroll
            for (int i=0;i<8;i++) dst[i]=src[i];
        }
        __syncthreads();
        #pragma unroll
        for (int j=0;j<64;j++){
            float p = s[j];
            const float4* vp = (const float4*)&KV[j][quar*32];
            #pragma unroll
            for (int i=0;i<8;i++){
                float4 vv = vp[i];
                o[4*i+0]+=p*vv.x; o[4*i+1]+=p*vv.y;
                o[4*i+2]+=p*vv.z; o[4*i+3]+=p*vv.w;
            }
        }
    }
    float invl = 1.f/l;
    float4* op = (float4*)&g_attn[(size_t)qrow*HID + h*HDIM + quar*32];
    #pragma unroll
    for (int i=0;i<8;i++)
        op[i] = make_float4(o[4*i+0]*invl, o[4*i+1]*invl, o[4*i+2]*invl, o[4*i+3]*invl);
}

// ---------------- routing: softmax over 8 logits, top-2 ----------------
__global__ void route_kernel(const float* __restrict__ gate_w)
{
    int t = blockIdx.x;
    int wid = threadIdx.x >> 5, lane = threadIdx.x & 31;
    __shared__ float slog[NEXP];
    const float* x  = g_x2 + (size_t)t*HID;
    const float* gw = gate_w + (size_t)wid*HID;
    float acc = 0.f;
    for (int i = lane; i < HID; i += 32) acc += x[i]*gw[i];
    #pragma unroll
    for (int o=16;o;o>>=1) acc += __shfl_xor_sync(0xffffffffu, acc, o);
    if (lane == 0) slog[wid] = acc;
    __syncthreads();
    if (threadIdx.x == 0){
        float mx = slog[0];
        for (int e=1;e<NEXP;e++) mx = fmaxf(mx, slog[e]);
        float p[NEXP]; float se = 0.f;
        for (int e=0;e<NEXP;e++){ p[e] = expf(slog[e]-mx); se += p[e]; }
        float inv = 1.f/se;
        for (int e=0;e<NEXP;e++) p[e] *= inv;
        int i1 = 0;
        for (int e=1;e<NEXP;e++) if (p[e] > p[i1]) i1 = e;
        int i2 = (i1==0) ? 1 : 0;
        for (int e=0;e<NEXP;e++) if (e!=i1 && p[e] > p[i2]) i2 = e;
        float v1 = p[i1], v2 = p[i2], s2 = 1.f/(v1+v2);
        g_topi[2*t]=i1; g_topi[2*t+1]=i2;
        g_topv[2*t]=v1*s2; g_topv[2*t+1]=v2*s2;
    }
}

// ---------------- deterministic per-expert token lists (one block) ----------------
__global__ void assign_kernel()
{
    __shared__ int scn[256];
    int tid = threadIdx.x;
    int base = 0;
    for (int e=0;e<NEXP;e++){
        int fl[8]; float fw[8];
        int local = 0;
        #pragma unroll
        for (int j=0;j<8;j++){
            int t = tid*8 + j;
            int a = g_topi[2*t], b = g_topi[2*t+1];
            float w = 0.f; int f = 0;
            if (a==e){ w += g_topv[2*t];   f = 1; }
            if (b==e){ w += g_topv[2*t+1]; f = 1; }
            fl[j]=f; fw[j]=w; local += f;
        }
        scn[tid]=local;
        __syncthreads();
        for (int d=1; d<256; d<<=1){          // Kogge-Stone inclusive scan
            int v = (tid>=d) ? scn[tid-d] : 0;
            __syncthreads();
            scn[tid] += v;
            __syncthreads();
        }
        int pos   = base + scn[tid] - local;  // exclusive prefix
        int total = scn[255];
        #pragma unroll
        for (int j=0;j<8;j++){
            if (fl[j]){ g_tok[pos]=tid*8+j; g_wgt[pos]=fw[j]; pos++; }
        }
        if (tid==0){ g_cnt[e]=total; g_off[e]=base; }
        base += total;
        __syncthreads();
    }
}

// ---------------- MoE up/gate projections with row gather ----------------
// which 0: C=g_t1 (w1) | 1: C=g_t3 (w3)
__global__ __launch_bounds__(256) void sgemm_moe_in(const float* __restrict__ Wbase, int which)
{
    int z = blockIdx.z;
    int cnt = g_cnt[z];
    int m0 = blockIdx.y*BM;
    if (m0 >= cnt) return;
    int off = g_off[z];
    const float* Bmat = Wbase + (size_t)z*FFD*HID;     // [FFD, HID]
    float* C = which ? g_t3 : g_t1;
    const int K = HID;
    __shared__ float As[BKK][BM];
    __shared__ float Bs[BKK][BN];
    int tid = threadIdx.x;
    int n0 = blockIdx.x*BN;
    int tx = tid & 15, ty = tid >> 4;
    int r0 = tid >> 2, kc = (tid & 3)*4;
    int r1 = r0 + 64;
    int gi0 = off + min(m0+r0, cnt-1);                 // clamped: garbage rows never stored
    int gi1 = off + min(m0+r1, cnt-1);
    const float* Ap0 = g_x2 + (size_t)g_tok[gi0]*K + kc;
    const float* Ap1 = g_x2 + (size_t)g_tok[gi1]*K + kc;
    const float* Bp0 = Bmat + (size_t)(n0+r0)*K + kc;
    const float* Bp1 = Bmat + (size_t)(n0+r1)*K + kc;
    float acc[8][8];
    #pragma unroll
    for (int i=0;i<8;i++)
        #pragma unroll
        for (int j=0;j<8;j++) acc[i][j]=0.f;
    for (int k0=0;k0<K;k0+=BKK){
        float4 a0 = *(const float4*)(Ap0 + k0);
        float4 a1 = *(const float4*)(Ap1 + k0);
        float4 b0 = *(const float4*)(Bp0 + k0);
        float4 b1 = *(const float4*)(Bp1 + k0);
        As[kc+0][r0]=a0.x; As[kc+1][r0]=a0.y; As[kc+2][r0]=a0.z; As[kc+3][r0]=a0.w;
        As[kc+0][r1]=a1.x; As[kc+1][r1]=a1.y; As[kc+2][r1]=a1.z; As[kc+3][r1]=a1.w;
        Bs[kc+0][r0]=b0.x; Bs[kc+1][r0]=b0.y; Bs[kc+2][r0]=b0.z; Bs[kc+3][r0]=b0.w;
        Bs[kc+0][r1]=b1.x; Bs[kc+1][r1]=b1.y; Bs[kc+2][r1]=b1.z; Bs[kc+3][r1]=b1.w;
        __syncthreads();
        #pragma unroll
        for (int k=0;k<BKK;k++){
            float a[8], b[8];
            *(float4*)&a[0] = *(const float4*)&As[k][ty*8];
            *(float4*)&a[4] = *(const float4*)&As[k][ty*8+4];
            *(float4*)&b[0] = *(const float4*)&Bs[k][tx*8];
            *(float4*)&b[4] = *(const float4*)&Bs[k][tx*8+4];
            #pragma unroll
            for (int i=0;i<8;i++)
                #pragma unroll
                for (int j=0;j<8;j++)
                    acc[i][j] += a[i]*b[j];
        }
        __syncthreads();
    }
    #pragma unroll
    for (int i=0;i<8;i++){
        int r = m0 + ty*8 + i;
        if (r < cnt){
            float* cp = C + (size_t)(off+r)*FFD + n0 + tx*8;
            #pragma unroll
            for (int j=0;j<8;j++) cp[j] = acc[i][j];
        }
    }
}

// ---------------- swiglu: g_t1 = silu(g_t1)*g_t3 ----------------
__global__ void swiglu_kernel()
{
    size_t i = (size_t)blockIdx.x*256 + threadIdx.x;
    float a = g_t1[i], b = g_t3[i];
    float sg = 1.f/(1.f + __expf(-a));
    g_t1[i] = a*sg*b;
}

// ---------------- base: out = h ----------------
__global__ void copy_h_kernel(float* __restrict__ out)
{
    int i = blockIdx.x*256 + threadIdx.x;
    out[i] = g_h[i];
}

// ---------------- MoE down projection with weighted atomic scatter ----------------
__global__ __launch_bounds__(256) void sgemm_moe_out(const float* __restrict__ W2, float* __restrict__ out)
{
    int z = blockIdx.z;
    int cnt = g_cnt[z];
    int m0 = blockIdx.y*BM;
    if (m0 >= cnt) return;
    int off = g_off[z];
    const float* Bmat = W2 + (size_t)z*HID*FFD;        // [HID, FFD]
    const int K = FFD;
    const int N = HID;
    __shared__ float As[BKK][BM];
    __shared__ float Bs[BKK][BN];
    int tid = threadIdx.x;
    int n0 = blockIdx.x*BN;
    int tx = tid & 15, ty = tid >> 4;
    int r0 = tid >> 2, kc = (tid & 3)*4;
    int r1 = r0 + 64;
    int ai0 = off + min(m0+r0, cnt-1);                 // clamped rows (never stored)
    int ai1 = off + min(m0+r1, cnt-1);
    const float* Ap0 = g_t1 + (size_t)ai0*K + kc;
    const float* Ap1 = g_t1 + (size_t)ai1*K + kc;
    const float* Bp0 = Bmat + (size_t)(n0+r0)*K + kc;
    const float* Bp1 = Bmat + (size_t)(n0+r1)*K + kc;
    float acc[8][8];
    #pragma unroll
    for (int i=0;i<8;i++)
        #pragma unroll
        for (int j=0;j<8;j++) acc[i][j]=0.f;
    for (int k0=0;k0<K;k0+=BKK){
        float4 a0 = *(const float4*)(Ap0 + k0);
        float4 a1 = *(const float4*)(Ap1 + k0);
        float4 b0 = *(const float4*)(Bp0 + k0);
        float4 b1 = *(const float4*)(Bp1 + k0);
        As[kc+0][r0]=a0.x; As[kc+1][r0]=a0.y; As[kc+2][r0]=a0.z; As[kc+3][r0]=a0.w;
        As[kc+0][r1]=a1.x; As[kc+1][r1]=a1.y; As[kc+2][r1]=a1.z; As[kc+3][r1]=a1.w;
        Bs[kc+0][r0]=b0.x; Bs[kc+1][r0]=b0.y; Bs[kc+2][r0]=b0.z; Bs[kc+3][r0]=b0.w;
        Bs[kc+0][r1]=b1.x; Bs[kc+1][r1]=b1.y; Bs[kc+2][r1]=b1.z; Bs[kc+3][r1]=b1.w;
        __syncthreads();
        #pragma unroll
        for (int k=0;k<BKK;k++){
            float a[8], b[8];
            *(float4*)&a[0] = *(const float4*)&As[k][ty*8];
            *(float4*)&a[4] = *(const float4*)&As[k][ty*8+4];
            *(float4*)&b[0] = *(const float4*)&Bs[k][tx*8];
            *(float4*)&b[4] = *(const float4*)&Bs[k][tx*8+4];
            #pragma unroll
            for (int i=0;i<8;i++)
                #pragma unroll
                for (int j=0;j<8;j++)
                    acc[i][j] += a[i]*b[j];
        }
        __syncthreads();
    }
    #pragma unroll
    for (int i=0;i<8;i++){
        int r = m0 + ty*8 + i;
        if (r < cnt){
            int tok = g_tok[off+r];
            float w = g_wgt[off+r];
            float* op = out + (size_t)tok*HID + n0 + tx*8;
            #pragma unroll
            for (int j=0;j<8;j++) atomicAdd(&op[j], w*acc[i][j]);
        }
    }
}

// ---------------- launch ----------------
extern "C" void kernel_launch(void* const* d_in, const int* in_sizes, int n_in,
                              void* d_out, int out_size)
{
    (void)in_sizes; (void)n_in; (void)out_size;
    const float* hidden = (const float*)d_in[0];
    const float* ln1_w  = (const float*)d_in[1];
    const float* ln2_w  = (const float*)d_in[2];
    const float* q_w    = (const float*)d_in[3];
    const float* k_w    = (const float*)d_in[4];
    const float* v_w    = (const float*)d_in[5];
    const float* o_w    = (const float*)d_in[6];
    const float* gate_w = (const float*)d_in[7];
    const float* w1     = (const float*)d_in[8];   // setup_inputs dict order: w1, w3, w2
    const float* w3     = (const float*)d_in[9];
    const float* w2     = (const float*)d_in[10];
    float* out = (float*)d_out;

    rmsnorm_kernel<<<SEQ,256>>>(hidden, ln1_w, 0);
    sgemm_dense<<<dim3(HID/BN,   SEQ/BM),256>>>(q_w, nullptr, 0, HID);
    sgemm_dense<<<dim3(KVDIM/BN, SEQ/BM),256>>>(k_w, nullptr, 1, KVDIM);
    sgemm_dense<<<dim3(KVDIM/BN, SEQ/BM),256>>>(v_w, nullptr, 2, KVDIM);
    rope_kernel<<<(SEQ*(HID/2))/256,  256>>>(0);
    rope_kernel<<<(SEQ*(KVDIM/2))/256,256>>>(1);
    flash_attn_kernel<<<dim3(SEQ/64, NHEAD),256>>>();
    sgemm_dense<<<dim3(HID/BN, SEQ/BM),256>>>(o_w, hidden, 3, HID);   // g_h = attn@o_w^T + hidden
    rmsnorm_kernel<<<SEQ,256>>>(hidden, ln2_w, 1);
    route_kernel<<<SEQ,256>>>(gate_w);
    assign_kernel<<<1,256>>>();
    sgemm_moe_in<<<dim3(FFD/BN, SEQ/BM, NEXP),256>>>(w1, 0);
    sgemm_moe_in<<<dim3(FFD/BN, SEQ/BM, NEXP),256>>>(w3, 1);
    swiglu_kernel<<<(NASSIGN*FFD)/256,256>>>();
    copy_h_kernel<<<(SEQ*HID)/256,256>>>(out);
    sgemm_moe_out<<<dim3(HID/BN, SEQ/BM, NEXP),256>>>(w2, out);
}